// round 2
// baseline (speedup 1.0000x reference)
#include <cuda_runtime.h>
#include <math.h>

// Problem constants
#define CB 2
#define CS 1024
#define CD 1024
#define CH 16
#define CDH 64
// M rows of the token-major GEMMs
#define CM (CB * CS)          // 2048
#define CN_QKV (3 * CD)       // 3072

// ---------------------------------------------------------------------------
// Scratch (static __device__ arrays; no allocation allowed)
// ---------------------------------------------------------------------------
__device__ float g_Q[CB * CH * CS * CDH];              // 8 MB (pre-scaled by 1/sqrt(DH))
__device__ float g_K[CB * CH * CS * CDH];              // 8 MB
__device__ float g_V[CB * CH * CS * CDH];              // 8 MB
__device__ float g_P[(size_t)CB * CH * CS * CS];       // 134 MB scores / probs
__device__ float g_O[CB * CS * CD];                    // 8 MB attention output [B,S,D]

// ---------------------------------------------------------------------------
// Kernel 1: fused QKV projection.  C[m,e] = sum_k X[m,k] * Wqkv[e,k]
// M=2048, N=3072, K=1024.  128x128 tile, BK=8, 256 threads, 8x8 per thread.
// Epilogue scatters into Q (scaled by 0.125), K, V in [B,H,S,DH] layout.
// ---------------------------------------------------------------------------
__global__ __launch_bounds__(256) void k_qkv(const float* __restrict__ X,
                                             const float* __restrict__ W) {
    __shared__ __align__(16) float As[8][128];
    __shared__ __align__(16) float Bs[8][128];
    const int tid = threadIdx.x;
    const int m0 = blockIdx.y * 128;
    const int n0 = blockIdx.x * 128;
    const int lr = tid >> 1;
    const int lc = (tid & 1) << 2;
    const int tx = tid & 15;
    const int ty = tid >> 4;

    const float* ap = X + (size_t)(m0 + lr) * CD + lc;
    const float* bp = W + (size_t)(n0 + lr) * CD + lc;

    float acc[8][8];
#pragma unroll
    for (int i = 0; i < 8; i++)
#pragma unroll
        for (int j = 0; j < 8; j++) acc[i][j] = 0.f;

    for (int k0 = 0; k0 < CD; k0 += 8) {
        float4 av = *reinterpret_cast<const float4*>(ap + k0);
        float4 bv = *reinterpret_cast<const float4*>(bp + k0);
        __syncthreads();
        As[lc + 0][lr] = av.x; As[lc + 1][lr] = av.y;
        As[lc + 2][lr] = av.z; As[lc + 3][lr] = av.w;
        Bs[lc + 0][lr] = bv.x; Bs[lc + 1][lr] = bv.y;
        Bs[lc + 2][lr] = bv.z; Bs[lc + 3][lr] = bv.w;
        __syncthreads();
#pragma unroll
        for (int k = 0; k < 8; k++) {
            float4 a0 = *reinterpret_cast<const float4*>(&As[k][ty * 8]);
            float4 a1 = *reinterpret_cast<const float4*>(&As[k][ty * 8 + 4]);
            float4 b0 = *reinterpret_cast<const float4*>(&Bs[k][tx * 8]);
            float4 b1 = *reinterpret_cast<const float4*>(&Bs[k][tx * 8 + 4]);
            float ra[8] = {a0.x, a0.y, a0.z, a0.w, a1.x, a1.y, a1.z, a1.w};
            float rb[8] = {b0.x, b0.y, b0.z, b0.w, b1.x, b1.y, b1.z, b1.w};
#pragma unroll
            for (int i = 0; i < 8; i++)
#pragma unroll
                for (int j = 0; j < 8; j++)
                    acc[i][j] = fmaf(ra[i], rb[j], acc[i][j]);
        }
    }

#pragma unroll
    for (int i = 0; i < 8; i++) {
        int m = m0 + ty * 8 + i;
        int b = m >> 10;
        int s = m & 1023;
#pragma unroll
        for (int j = 0; j < 8; j++) {
            int e = n0 + tx * 8 + j;
            int c = e >> 10;            // 0=Q, 1=K, 2=V
            int h = (e >> 6) & 15;
            int dh = e & 63;
            int idx = (((b * CH + h) * CS) + s) * CDH + dh;
            float v = acc[i][j];
            if (c == 0)      g_Q[idx] = v * 0.125f;   // fold 1/sqrt(64)
            else if (c == 1) g_K[idx] = v;
            else             g_V[idx] = v;
        }
    }
}

// ---------------------------------------------------------------------------
// Kernel 2: scores.  Per (b,h): P[m,n] = sum_k Q[m,k] * K[n,k], K-dim = 64.
// Grid (8, 8, 32).  Same 128x128 tiling, lda = 64.
// ---------------------------------------------------------------------------
__global__ __launch_bounds__(256) void k_scores() {
    __shared__ __align__(16) float As[8][128];
    __shared__ __align__(16) float Bs[8][128];
    const int bh = blockIdx.z;
    const float* Qp = g_Q + (size_t)bh * CS * CDH;
    const float* Kp = g_K + (size_t)bh * CS * CDH;
    float* Cp = g_P + (size_t)bh * CS * CS;

    const int tid = threadIdx.x;
    const int m0 = blockIdx.y * 128;
    const int n0 = blockIdx.x * 128;
    const int lr = tid >> 1;
    const int lc = (tid & 1) << 2;
    const int tx = tid & 15;
    const int ty = tid >> 4;

    const float* ap = Qp + (size_t)(m0 + lr) * CDH + lc;
    const float* bp = Kp + (size_t)(n0 + lr) * CDH + lc;

    float acc[8][8];
#pragma unroll
    for (int i = 0; i < 8; i++)
#pragma unroll
        for (int j = 0; j < 8; j++) acc[i][j] = 0.f;

    for (int k0 = 0; k0 < CDH; k0 += 8) {
        float4 av = *reinterpret_cast<const float4*>(ap + k0);
        float4 bv = *reinterpret_cast<const float4*>(bp + k0);
        __syncthreads();
        As[lc + 0][lr] = av.x; As[lc + 1][lr] = av.y;
        As[lc + 2][lr] = av.z; As[lc + 3][lr] = av.w;
        Bs[lc + 0][lr] = bv.x; Bs[lc + 1][lr] = bv.y;
        Bs[lc + 2][lr] = bv.z; Bs[lc + 3][lr] = bv.w;
        __syncthreads();
#pragma unroll
        for (int k = 0; k < 8; k++) {
            float4 a0 = *reinterpret_cast<const float4*>(&As[k][ty * 8]);
            float4 a1 = *reinterpret_cast<const float4*>(&As[k][ty * 8 + 4]);
            float4 b0 = *reinterpret_cast<const float4*>(&Bs[k][tx * 8]);
            float4 b1 = *reinterpret_cast<const float4*>(&Bs[k][tx * 8 + 4]);
            float ra[8] = {a0.x, a0.y, a0.z, a0.w, a1.x, a1.y, a1.z, a1.w};
            float rb[8] = {b0.x, b0.y, b0.z, b0.w, b1.x, b1.y, b1.z, b1.w};
#pragma unroll
            for (int i = 0; i < 8; i++)
#pragma unroll
                for (int j = 0; j < 8; j++)
                    acc[i][j] = fmaf(ra[i], rb[j], acc[i][j]);
        }
    }

#pragma unroll
    for (int i = 0; i < 8; i++) {
        int m = m0 + ty * 8 + i;
#pragma unroll
        for (int j = 0; j < 8; j++) {
            int n = n0 + tx * 8 + j;
            Cp[(size_t)m * CS + n] = acc[i][j];
        }
    }
}

// ---------------------------------------------------------------------------
// Kernel 3: row softmax.  One block per row (32768 rows), 256 threads,
// exactly one float4 per thread.
// ---------------------------------------------------------------------------
__global__ __launch_bounds__(256) void k_softmax() {
    float* p = g_P + (size_t)blockIdx.x * CS;
    __shared__ float red[256];
    const int tid = threadIdx.x;
    float4* p4 = reinterpret_cast<float4*>(p);
    float4 v = p4[tid];

    float mx = fmaxf(fmaxf(v.x, v.y), fmaxf(v.z, v.w));
    red[tid] = mx;
    __syncthreads();
    for (int s = 128; s > 0; s >>= 1) {
        if (tid < s) red[tid] = fmaxf(red[tid], red[tid + s]);
        __syncthreads();
    }
    float m = red[0];
    __syncthreads();

    v.x = expf(v.x - m);
    v.y = expf(v.y - m);
    v.z = expf(v.z - m);
    v.w = expf(v.w - m);

    red[tid] = v.x + v.y + v.z + v.w;
    __syncthreads();
    for (int s = 128; s > 0; s >>= 1) {
        if (tid < s) red[tid] += red[tid + s];
        __syncthreads();
    }
    float inv = 1.0f / red[0];
    v.x *= inv; v.y *= inv; v.z *= inv; v.w *= inv;
    p4[tid] = v;
}

// ---------------------------------------------------------------------------
// Kernel 4: PV.  Per (b,h): O[m,n] = sum_k P[m,k] * V[k,n]; M=1024, N=64,
// K=1024.  Block tile 128x64, BK=16, 256 threads, 8x4 per thread.
// Writes directly into [B,S,D] layout.
// ---------------------------------------------------------------------------
__global__ __launch_bounds__(256) void k_pv() {
    __shared__ __align__(16) float Ps[16][128];
    __shared__ __align__(16) float Vs[16][64];
    const int bh = blockIdx.z;
    const int b = bh >> 4;
    const int h = bh & 15;
    const float* Pp = g_P + (size_t)bh * CS * CS;
    const float* Vp = g_V + (size_t)bh * CS * CDH;

    const int tid = threadIdx.x;
    const int m0 = blockIdx.y * 128;
    const int pr = tid >> 2;            // 0..63
    const int pc = (tid & 3) << 2;      // 0,4,8,12
    const int vr = tid >> 4;            // 0..15
    const int vc = (tid & 15) << 2;     // 0..60
    const int tx = tid & 15;            // col group (4 cols)
    const int ty = tid >> 4;            // row group (8 rows)

    float acc[8][4];
#pragma unroll
    for (int i = 0; i < 8; i++)
#pragma unroll
        for (int j = 0; j < 4; j++) acc[i][j] = 0.f;

    for (int k0 = 0; k0 < CS; k0 += 16) {
        float4 a0 = *reinterpret_cast<const float4*>(Pp + (size_t)(m0 + pr) * CS + k0 + pc);
        float4 a1 = *reinterpret_cast<const float4*>(Pp + (size_t)(m0 + 64 + pr) * CS + k0 + pc);
        float4 bv = *reinterpret_cast<const float4*>(Vp + (size_t)(k0 + vr) * CDH + vc);
        __syncthreads();
        Ps[pc + 0][pr] = a0.x; Ps[pc + 1][pr] = a0.y;
        Ps[pc + 2][pr] = a0.z; Ps[pc + 3][pr] = a0.w;
        Ps[pc + 0][64 + pr] = a1.x; Ps[pc + 1][64 + pr] = a1.y;
        Ps[pc + 2][64 + pr] = a1.z; Ps[pc + 3][64 + pr] = a1.w;
        *reinterpret_cast<float4*>(&Vs[vr][vc]) = bv;
        __syncthreads();
#pragma unroll
        for (int k = 0; k < 16; k++) {
            float4 a0r = *reinterpret_cast<const float4*>(&Ps[k][ty * 8]);
            float4 a1r = *reinterpret_cast<const float4*>(&Ps[k][ty * 8 + 4]);
            float4 br  = *reinterpret_cast<const float4*>(&Vs[k][tx * 4]);
            float ra[8] = {a0r.x, a0r.y, a0r.z, a0r.w, a1r.x, a1r.y, a1r.z, a1r.w};
            float rb[4] = {br.x, br.y, br.z, br.w};
#pragma unroll
            for (int i = 0; i < 8; i++)
#pragma unroll
                for (int j = 0; j < 4; j++)
                    acc[i][j] = fmaf(ra[i], rb[j], acc[i][j]);
        }
    }

#pragma unroll
    for (int i = 0; i < 8; i++) {
        int s = m0 + ty * 8 + i;
#pragma unroll
        for (int j = 0; j < 4; j++) {
            int n = tx * 4 + j;
            g_O[((size_t)(b * CS + s)) * CD + h * CDH + n] = acc[i][j];
        }
    }
}

// ---------------------------------------------------------------------------
// Kernel 5: output projection.  C[m,e] = sum_k O[m,k] * Wout[e,k]
// M=2048, N=1024, K=1024.  Same 128x128 NT tiling; writes d_out.
// ---------------------------------------------------------------------------
__global__ __launch_bounds__(256) void k_out(const float* __restrict__ W,
                                             float* __restrict__ C) {
    __shared__ __align__(16) float As[8][128];
    __shared__ __align__(16) float Bs[8][128];
    const int tid = threadIdx.x;
    const int m0 = blockIdx.y * 128;
    const int n0 = blockIdx.x * 128;
    const int lr = tid >> 1;
    const int lc = (tid & 1) << 2;
    const int tx = tid & 15;
    const int ty = tid >> 4;

    const float* ap = g_O + (size_t)(m0 + lr) * CD + lc;
    const float* bp = W + (size_t)(n0 + lr) * CD + lc;

    float acc[8][8];
#pragma unroll
    for (int i = 0; i < 8; i++)
#pragma unroll
        for (int j = 0; j < 8; j++) acc[i][j] = 0.f;

    for (int k0 = 0; k0 < CD; k0 += 8) {
        float4 av = *reinterpret_cast<const float4*>(ap + k0);
        float4 bv = *reinterpret_cast<const float4*>(bp + k0);
        __syncthreads();
        As[lc + 0][lr] = av.x; As[lc + 1][lr] = av.y;
        As[lc + 2][lr] = av.z; As[lc + 3][lr] = av.w;
        Bs[lc + 0][lr] = bv.x; Bs[lc + 1][lr] = bv.y;
        Bs[lc + 2][lr] = bv.z; Bs[lc + 3][lr] = bv.w;
        __syncthreads();
#pragma unroll
        for (int k = 0; k < 8; k++) {
            float4 a0 = *reinterpret_cast<const float4*>(&As[k][ty * 8]);
            float4 a1 = *reinterpret_cast<const float4*>(&As[k][ty * 8 + 4]);
            float4 b0 = *reinterpret_cast<const float4*>(&Bs[k][tx * 8]);
            float4 b1 = *reinterpret_cast<const float4*>(&Bs[k][tx * 8 + 4]);
            float ra[8] = {a0.x, a0.y, a0.z, a0.w, a1.x, a1.y, a1.z, a1.w};
            float rb[8] = {b0.x, b0.y, b0.z, b0.w, b1.x, b1.y, b1.z, b1.w};
#pragma unroll
            for (int i = 0; i < 8; i++)
#pragma unroll
                for (int j = 0; j < 8; j++)
                    acc[i][j] = fmaf(ra[i], rb[j], acc[i][j]);
        }
    }

#pragma unroll
    for (int i = 0; i < 8; i++) {
        int m = m0 + ty * 8 + i;
#pragma unroll
        for (int j = 0; j < 8; j++) {
            int e = n0 + tx * 8 + j;
            C[(size_t)m * CD + e] = acc[i][j];
        }
    }
}

// ---------------------------------------------------------------------------
// Launch
// ---------------------------------------------------------------------------
extern "C" void kernel_launch(void* const* d_in, const int* in_sizes, int n_in,
                              void* d_out, int out_size) {
    const float* x    = (const float*)d_in[0];  // [B,S,D]
    const float* Wqkv = (const float*)d_in[1];  // [3D,D]
    const float* Wout = (const float*)d_in[2];  // [D,D]
    float* out = (float*)d_out;                 // [B,S,D]

    (void)in_sizes; (void)n_in; (void)out_size;

    // 1) fused QKV projection -> Q(scaled), K, V  [B,H,S,DH]
    k_qkv<<<dim3(CN_QKV / 128, CM / 128), 256>>>(x, Wqkv);
    // 2) scores = Q @ K^T  (per b,h)
    k_scores<<<dim3(CS / 128, CS / 128, CB * CH), 256>>>();
    // 3) row softmax
    k_softmax<<<CB * CH * CS, 256>>>();
    // 4) out = P @ V  -> [B,S,D]
    k_pv<<<dim3(1, CS / 128, CB * CH), 256>>>();
    // 5) output projection -> d_out
    k_out<<<dim3(CD / 128, CM / 128), 256>>>(Wout, out);
}

// round 3
// speedup vs baseline: 2.2302x; 2.2302x over previous
#include <cuda_runtime.h>
#include <stdint.h>

// Problem constants
#define CB 2
#define CS 1024
#define CD 1024
#define CH 16
#define CDH 64
#define CM (CB * CS)          // 2048
#define CN_QKV (3 * CD)       // 3072

// ---------------------------------------------------------------------------
// Scratch (static __device__ arrays; no allocation allowed)
// ---------------------------------------------------------------------------
__device__ float g_Q[CB * CH * CS * CDH];              // pre-scaled by 1/sqrt(DH)
__device__ float g_K[CB * CH * CS * CDH];
__device__ float g_V[CB * CH * CS * CDH];              // [b,h][s][dh]
__device__ float g_P[(size_t)CB * CH * CS * CS];       // 134 MB scores / probs
__device__ float g_O[CB * CS * CD];                    // attention out [B,S,D]

// ---------------------------------------------------------------------------
// tf32 helpers
// ---------------------------------------------------------------------------
__device__ __forceinline__ uint32_t f2tf(float x) {
    uint32_t u;
    asm("cvt.rna.tf32.f32 %0, %1;" : "=r"(u) : "f"(x));
    return u;
}

__device__ __forceinline__ void mma8(float* c, const uint32_t* a, const uint32_t* b) {
    asm volatile(
        "mma.sync.aligned.m16n8k8.row.col.f32.tf32.tf32.f32 "
        "{%0,%1,%2,%3},{%4,%5,%6,%7},{%8,%9},{%0,%1,%2,%3};"
        : "+f"(c[0]), "+f"(c[1]), "+f"(c[2]), "+f"(c[3])
        : "r"(a[0]), "r"(a[1]), "r"(a[2]), "r"(a[3]), "r"(b[0]), "r"(b[1]));
}

// ---------------------------------------------------------------------------
// Generic NT tf32 GEMM: C[M,N] = A[M,K] * B[N,K]^T
// Block tile 128x128, BK=16, 256 threads (8 warps in 2(M) x 4(N)), warp 64x32.
// EPI 0: A=x, B=Wqkv -> scatter to g_Q(*0.125)/g_K/g_V   (K=1024)
// EPI 1: A=g_Q(bh), B=g_K(bh) -> g_P(bh)                  (K=64, z-batched)
// EPI 2: A=g_O, B=Wout -> Cg                              (K=1024)
// ---------------------------------------------------------------------------
template <int EPI>
__global__ __launch_bounds__(256) void k_gemm_nt(const float* __restrict__ Ag,
                                                 const float* __restrict__ Bg,
                                                 float* __restrict__ Cg, int K) {
    constexpr int BM = 128, BN = 128, BK = 16, SA = 136;
    __shared__ uint32_t As[BK][SA];   // [k][m], stride 136 => conflict-free frags
    __shared__ uint32_t Bs[BK][SA];   // [k][n]

    const float* A;
    const float* B;
    float* Co = nullptr;
    if constexpr (EPI == 1) {
        size_t off = (size_t)blockIdx.z * CS * CDH;
        A = g_Q + off;
        B = g_K + off;
        Co = g_P + (size_t)blockIdx.z * CS * CS;
    } else if constexpr (EPI == 2) {
        A = g_O;
        B = Bg;
        Co = Cg;
    } else {
        A = Ag;
        B = Bg;
    }

    const int tid = threadIdx.x;
    const int m0 = blockIdx.y * BM;
    const int n0 = blockIdx.x * BN;
    const int warp = tid >> 5, lane = tid & 31;
    const int wm = (warp & 1) * 64;       // warp m-offset
    const int wn = (warp >> 1) * 32;      // warp n-offset
    const int gid = lane >> 2, tig = lane & 3;
    const int lr = tid >> 2;              // loader row 0..63
    const int lk = (tid & 3) * 4;         // loader k offset

    float acc[4][4][4] = {};

    const float* a0p = A + (size_t)(m0 + lr) * K + lk;
    const float* a1p = A + (size_t)(m0 + 64 + lr) * K + lk;
    const float* b0p = B + (size_t)(n0 + lr) * K + lk;
    const float* b1p = B + (size_t)(n0 + 64 + lr) * K + lk;

    for (int k0 = 0; k0 < K; k0 += BK) {
        float4 av0 = *reinterpret_cast<const float4*>(a0p + k0);
        float4 av1 = *reinterpret_cast<const float4*>(a1p + k0);
        float4 bv0 = *reinterpret_cast<const float4*>(b0p + k0);
        float4 bv1 = *reinterpret_cast<const float4*>(b1p + k0);
        __syncthreads();
        As[lk + 0][lr] = f2tf(av0.x); As[lk + 1][lr] = f2tf(av0.y);
        As[lk + 2][lr] = f2tf(av0.z); As[lk + 3][lr] = f2tf(av0.w);
        As[lk + 0][lr + 64] = f2tf(av1.x); As[lk + 1][lr + 64] = f2tf(av1.y);
        As[lk + 2][lr + 64] = f2tf(av1.z); As[lk + 3][lr + 64] = f2tf(av1.w);
        Bs[lk + 0][lr] = f2tf(bv0.x); Bs[lk + 1][lr] = f2tf(bv0.y);
        Bs[lk + 2][lr] = f2tf(bv0.z); Bs[lk + 3][lr] = f2tf(bv0.w);
        Bs[lk + 0][lr + 64] = f2tf(bv1.x); Bs[lk + 1][lr + 64] = f2tf(bv1.y);
        Bs[lk + 2][lr + 64] = f2tf(bv1.z); Bs[lk + 3][lr + 64] = f2tf(bv1.w);
        __syncthreads();

#pragma unroll
        for (int kk = 0; kk < BK; kk += 8) {
            uint32_t af[4][4], bf[4][2];
#pragma unroll
            for (int mi = 0; mi < 4; mi++) {
                int m = wm + mi * 16 + gid;
                af[mi][0] = As[kk + tig][m];
                af[mi][1] = As[kk + tig][m + 8];
                af[mi][2] = As[kk + tig + 4][m];
                af[mi][3] = As[kk + tig + 4][m + 8];
            }
#pragma unroll
            for (int nj = 0; nj < 4; nj++) {
                int n = wn + nj * 8 + gid;
                bf[nj][0] = Bs[kk + tig][n];
                bf[nj][1] = Bs[kk + tig + 4][n];
            }
#pragma unroll
            for (int mi = 0; mi < 4; mi++)
#pragma unroll
                for (int nj = 0; nj < 4; nj++)
                    mma8(acc[mi][nj], af[mi], bf[nj]);
        }
    }

    // Epilogue: each (mi,nj) tile -> rows r0/r0+8, cols c0..c0+1 (float2)
#pragma unroll
    for (int mi = 0; mi < 4; mi++) {
        int r0 = m0 + wm + mi * 16 + gid;
#pragma unroll
        for (int nj = 0; nj < 4; nj++) {
            int c0 = n0 + wn + nj * 8 + 2 * tig;
            const float* cc = acc[mi][nj];
            if constexpr (EPI == 0) {
#pragma unroll
                for (int half = 0; half < 2; half++) {
                    int m = r0 + half * 8;
                    int b = m >> 10, s = m & 1023;
                    int creg = c0 >> 10;            // 0=Q 1=K 2=V
                    int h = (c0 >> 6) & 15, dh = c0 & 63;
                    size_t idx = (((size_t)(b * CH + h) * CS) + s) * CDH + dh;
                    float v0 = cc[half * 2], v1 = cc[half * 2 + 1];
                    if (creg == 0)
                        *reinterpret_cast<float2*>(g_Q + idx) =
                            make_float2(v0 * 0.125f, v1 * 0.125f);
                    else if (creg == 1)
                        *reinterpret_cast<float2*>(g_K + idx) = make_float2(v0, v1);
                    else
                        *reinterpret_cast<float2*>(g_V + idx) = make_float2(v0, v1);
                }
            } else {
                *reinterpret_cast<float2*>(Co + (size_t)r0 * 1024 + c0) =
                    make_float2(cc[0], cc[1]);
                *reinterpret_cast<float2*>(Co + (size_t)(r0 + 8) * 1024 + c0) =
                    make_float2(cc[2], cc[3]);
            }
        }
    }
}

// ---------------------------------------------------------------------------
// PV (NN): per (b,h)  O[m,n] = sum_k P[m,k] * V[k,n]; M=1024, N=64, K=1024.
// Block 128x64, BK=16, 256 threads (8 warps in 4(M) x 2(N)), warp 32x32.
// ---------------------------------------------------------------------------
__global__ __launch_bounds__(256) void k_pv() {
    constexpr int BM = 128, BK = 16, SA = 136, SB = 72;
    __shared__ uint32_t As[BK][SA];   // [k][m]
    __shared__ uint32_t Bs[BK][SB];   // [k][n]

    const int bh = blockIdx.z;
    const int b = bh >> 4, h = bh & 15;
    const float* A = g_P + (size_t)bh * CS * CS;
    const float* V = g_V + (size_t)bh * CS * CDH;

    const int tid = threadIdx.x;
    const int m0 = blockIdx.y * BM;
    const int warp = tid >> 5, lane = tid & 31;
    const int wm = (warp & 3) * 32;       // 4 warps along M
    const int wn = (warp >> 2) * 32;      // 2 warps along N
    const int gid = lane >> 2, tig = lane & 3;
    const int lr = tid >> 2;              // P loader row
    const int lk = (tid & 3) * 4;
    const int vk = tid >> 4;              // V loader: row k, 16 rows
    const int vn = (tid & 15) * 4;        // V loader: col

    float acc[2][4][4] = {};

    const float* a0p = A + (size_t)(m0 + lr) * CS + lk;
    const float* a1p = A + (size_t)(m0 + 64 + lr) * CS + lk;
    const float* vp = V + (size_t)vk * CDH + vn;

    for (int k0 = 0; k0 < CS; k0 += BK) {
        float4 av0 = *reinterpret_cast<const float4*>(a0p + k0);
        float4 av1 = *reinterpret_cast<const float4*>(a1p + k0);
        float4 bv = *reinterpret_cast<const float4*>(vp + (size_t)k0 * CDH);
        __syncthreads();
        As[lk + 0][lr] = f2tf(av0.x); As[lk + 1][lr] = f2tf(av0.y);
        As[lk + 2][lr] = f2tf(av0.z); As[lk + 3][lr] = f2tf(av0.w);
        As[lk + 0][lr + 64] = f2tf(av1.x); As[lk + 1][lr + 64] = f2tf(av1.y);
        As[lk + 2][lr + 64] = f2tf(av1.z); As[lk + 3][lr + 64] = f2tf(av1.w);
        uint4 bu;
        bu.x = f2tf(bv.x); bu.y = f2tf(bv.y); bu.z = f2tf(bv.z); bu.w = f2tf(bv.w);
        *reinterpret_cast<uint4*>(&Bs[vk][vn]) = bu;
        __syncthreads();

#pragma unroll
        for (int kk = 0; kk < BK; kk += 8) {
            uint32_t af[2][4], bf[4][2];
#pragma unroll
            for (int mi = 0; mi < 2; mi++) {
                int m = wm + mi * 16 + gid;
                af[mi][0] = As[kk + tig][m];
                af[mi][1] = As[kk + tig][m + 8];
                af[mi][2] = As[kk + tig + 4][m];
                af[mi][3] = As[kk + tig + 4][m + 8];
            }
#pragma unroll
            for (int nj = 0; nj < 4; nj++) {
                int n = wn + nj * 8 + gid;
                bf[nj][0] = Bs[kk + tig][n];
                bf[nj][1] = Bs[kk + tig + 4][n];
            }
#pragma unroll
            for (int mi = 0; mi < 2; mi++)
#pragma unroll
                for (int nj = 0; nj < 4; nj++)
                    mma8(acc[mi][nj], af[mi], bf[nj]);
        }
    }

#pragma unroll
    for (int mi = 0; mi < 2; mi++) {
        int s0 = m0 + wm + mi * 16 + gid;
#pragma unroll
        for (int nj = 0; nj < 4; nj++) {
            int n = wn + nj * 8 + 2 * tig;
            const float* cc = acc[mi][nj];
            float* o = g_O + ((size_t)(b * CS + s0)) * CD + h * CDH + n;
            *reinterpret_cast<float2*>(o) = make_float2(cc[0], cc[1]);
            *reinterpret_cast<float2*>(o + 8 * CD) = make_float2(cc[2], cc[3]);
        }
    }
}

// ---------------------------------------------------------------------------
// Row softmax: one block per row, 256 threads, one float4 each.
// ---------------------------------------------------------------------------
__global__ __launch_bounds__(256) void k_softmax() {
    float* p = g_P + (size_t)blockIdx.x * CS;
    __shared__ float red[256];
    const int tid = threadIdx.x;
    float4* p4 = reinterpret_cast<float4*>(p);
    float4 v = p4[tid];

    float mx = fmaxf(fmaxf(v.x, v.y), fmaxf(v.z, v.w));
    red[tid] = mx;
    __syncthreads();
    for (int s = 128; s > 0; s >>= 1) {
        if (tid < s) red[tid] = fmaxf(red[tid], red[tid + s]);
        __syncthreads();
    }
    float m = red[0];
    __syncthreads();

    v.x = __expf(v.x - m);
    v.y = __expf(v.y - m);
    v.z = __expf(v.z - m);
    v.w = __expf(v.w - m);

    red[tid] = v.x + v.y + v.z + v.w;
    __syncthreads();
    for (int s = 128; s > 0; s >>= 1) {
        if (tid < s) red[tid] += red[tid + s];
        __syncthreads();
    }
    float inv = 1.0f / red[0];
    v.x *= inv; v.y *= inv; v.z *= inv; v.w *= inv;
    p4[tid] = v;
}

// ---------------------------------------------------------------------------
// Launch
// ---------------------------------------------------------------------------
extern "C" void kernel_launch(void* const* d_in, const int* in_sizes, int n_in,
                              void* d_out, int out_size) {
    const float* x    = (const float*)d_in[0];  // [B,S,D]
    const float* Wqkv = (const float*)d_in[1];  // [3D,D]
    const float* Wout = (const float*)d_in[2];  // [D,D]
    float* out = (float*)d_out;                 // [B,S,D]

    (void)in_sizes; (void)n_in; (void)out_size;

    // 1) fused QKV projection -> Q(scaled), K, V  [B,H,S,DH]
    k_gemm_nt<0><<<dim3(CN_QKV / 128, CM / 128), 256>>>(x, Wqkv, nullptr, CD);
    // 2) scores = Q @ K^T  (per b,h)
    k_gemm_nt<1><<<dim3(CS / 128, CS / 128, CB * CH), 256>>>(nullptr, nullptr, nullptr, CDH);
    // 3) row softmax
    k_softmax<<<CB * CH * CS, 256>>>();
    // 4) out = P @ V  -> [B,S,D]
    k_pv<<<dim3(1, CS / 128, CB * CH), 256>>>();
    // 5) output projection -> d_out
    k_gemm_nt<2><<<dim3(CD / 128, CM / 128), 256>>>(nullptr, Wout, out, CD);
}

// round 4
// speedup vs baseline: 3.1504x; 1.4126x over previous
#include <cuda_runtime.h>
#include <stdint.h>

// Problem constants
#define CB 2
#define CS 1024
#define CD 1024
#define CH 16
#define CDH 64
#define CM (CB * CS)          // 2048
#define CN_QKV (3 * CD)       // 3072

// ---------------------------------------------------------------------------
// Scratch
// ---------------------------------------------------------------------------
__device__ float g_Q[CB * CH * CS * CDH];   // pre-scaled by 1/sqrt(DH)
__device__ float g_K[CB * CH * CS * CDH];
__device__ float g_V[CB * CH * CS * CDH];
__device__ float g_O[CB * CS * CD];         // attention out [B,S,D]

// ---------------------------------------------------------------------------
// tf32 helpers
// ---------------------------------------------------------------------------
__device__ __forceinline__ uint32_t f2tf(float x) {
    uint32_t u;
    asm("cvt.rna.tf32.f32 %0, %1;" : "=r"(u) : "f"(x));
    return u;
}

__device__ __forceinline__ void mma8(float* c, const uint32_t* a, const uint32_t* b) {
    asm volatile(
        "mma.sync.aligned.m16n8k8.row.col.f32.tf32.tf32.f32 "
        "{%0,%1,%2,%3},{%4,%5,%6,%7},{%8,%9},{%0,%1,%2,%3};"
        : "+f"(c[0]), "+f"(c[1]), "+f"(c[2]), "+f"(c[3])
        : "r"(a[0]), "r"(a[1]), "r"(a[2]), "r"(a[3]), "r"(b[0]), "r"(b[1]));
}

// ---------------------------------------------------------------------------
// NT tf32 GEMM with register-prefetch pipeline: C[M,N] = A[M,K] * B[N,K]^T
// Block 128x128, BK=16, 256 threads (2x4 warps), warp 64x32.
// EPI 0: A=x, B=Wqkv -> scatter g_Q(*0.125)/g_K/g_V
// EPI 2: A=g_O, B=Wout -> Cg
// ---------------------------------------------------------------------------
template <int EPI>
__global__ __launch_bounds__(256) void k_gemm_nt(const float* __restrict__ Ag,
                                                 const float* __restrict__ Bg,
                                                 float* __restrict__ Cg, int K) {
    constexpr int BM = 128, BK = 16, SA = 136;
    __shared__ uint32_t As[BK][SA];   // [k][m]
    __shared__ uint32_t Bs[BK][SA];   // [k][n]

    const float* A;
    const float* B;
    float* Co = nullptr;
    if constexpr (EPI == 2) {
        A = g_O; B = Bg; Co = Cg;
    } else {
        A = Ag; B = Bg;
    }

    const int tid = threadIdx.x;
    const int m0 = blockIdx.y * BM;
    const int n0 = blockIdx.x * BM;
    const int warp = tid >> 5, lane = tid & 31;
    const int wm = (warp & 1) * 64;
    const int wn = (warp >> 1) * 32;
    const int gid = lane >> 2, tig = lane & 3;
    const int lr = tid >> 2;
    const int lk = (tid & 3) * 4;

    float acc[4][4][4] = {};

    const float* a0p = A + (size_t)(m0 + lr) * K + lk;
    const float* a1p = A + (size_t)(m0 + 64 + lr) * K + lk;
    const float* b0p = B + (size_t)(n0 + lr) * K + lk;
    const float* b1p = B + (size_t)(n0 + 64 + lr) * K + lk;

    float4 av0 = *reinterpret_cast<const float4*>(a0p);
    float4 av1 = *reinterpret_cast<const float4*>(a1p);
    float4 bv0 = *reinterpret_cast<const float4*>(b0p);
    float4 bv1 = *reinterpret_cast<const float4*>(b1p);

    for (int k0 = 0;;) {
        __syncthreads();
        As[lk + 0][lr] = f2tf(av0.x); As[lk + 1][lr] = f2tf(av0.y);
        As[lk + 2][lr] = f2tf(av0.z); As[lk + 3][lr] = f2tf(av0.w);
        As[lk + 0][lr + 64] = f2tf(av1.x); As[lk + 1][lr + 64] = f2tf(av1.y);
        As[lk + 2][lr + 64] = f2tf(av1.z); As[lk + 3][lr + 64] = f2tf(av1.w);
        Bs[lk + 0][lr] = f2tf(bv0.x); Bs[lk + 1][lr] = f2tf(bv0.y);
        Bs[lk + 2][lr] = f2tf(bv0.z); Bs[lk + 3][lr] = f2tf(bv0.w);
        Bs[lk + 0][lr + 64] = f2tf(bv1.x); Bs[lk + 1][lr + 64] = f2tf(bv1.y);
        Bs[lk + 2][lr + 64] = f2tf(bv1.z); Bs[lk + 3][lr + 64] = f2tf(bv1.w);
        __syncthreads();

        k0 += BK;
        const bool more = (k0 < K);
        if (more) {   // prefetch next tile while computing current
            av0 = *reinterpret_cast<const float4*>(a0p + k0);
            av1 = *reinterpret_cast<const float4*>(a1p + k0);
            bv0 = *reinterpret_cast<const float4*>(b0p + k0);
            bv1 = *reinterpret_cast<const float4*>(b1p + k0);
        }

#pragma unroll
        for (int kk = 0; kk < BK; kk += 8) {
            uint32_t af[4][4], bf[4][2];
#pragma unroll
            for (int mi = 0; mi < 4; mi++) {
                int m = wm + mi * 16 + gid;
                af[mi][0] = As[kk + tig][m];
                af[mi][1] = As[kk + tig][m + 8];
                af[mi][2] = As[kk + tig + 4][m];
                af[mi][3] = As[kk + tig + 4][m + 8];
            }
#pragma unroll
            for (int nj = 0; nj < 4; nj++) {
                int n = wn + nj * 8 + gid;
                bf[nj][0] = Bs[kk + tig][n];
                bf[nj][1] = Bs[kk + tig + 4][n];
            }
#pragma unroll
            for (int mi = 0; mi < 4; mi++)
#pragma unroll
                for (int nj = 0; nj < 4; nj++)
                    mma8(acc[mi][nj], af[mi], bf[nj]);
        }
        if (!more) break;
    }

#pragma unroll
    for (int mi = 0; mi < 4; mi++) {
        int r0 = m0 + wm + mi * 16 + gid;
#pragma unroll
        for (int nj = 0; nj < 4; nj++) {
            int c0 = n0 + wn + nj * 8 + 2 * tig;
            const float* cc = acc[mi][nj];
            if constexpr (EPI == 0) {
#pragma unroll
                for (int half = 0; half < 2; half++) {
                    int m = r0 + half * 8;
                    int b = m >> 10, s = m & 1023;
                    int creg = c0 >> 10;            // 0=Q 1=K 2=V
                    int h = (c0 >> 6) & 15, dh = c0 & 63;
                    size_t idx = (((size_t)(b * CH + h) * CS) + s) * CDH + dh;
                    float v0 = cc[half * 2], v1 = cc[half * 2 + 1];
                    if (creg == 0)
                        *reinterpret_cast<float2*>(g_Q + idx) =
                            make_float2(v0 * 0.125f, v1 * 0.125f);
                    else if (creg == 1)
                        *reinterpret_cast<float2*>(g_K + idx) = make_float2(v0, v1);
                    else
                        *reinterpret_cast<float2*>(g_V + idx) = make_float2(v0, v1);
                }
            } else {
                *reinterpret_cast<float2*>(Co + (size_t)r0 * 1024 + c0) =
                    make_float2(cc[0], cc[1]);
                *reinterpret_cast<float2*>(Co + (size_t)(r0 + 8) * 1024 + c0) =
                    make_float2(cc[2], cc[3]);
            }
        }
    }
}

// ---------------------------------------------------------------------------
// Fused flash attention: per (b,h) q-tile of 64 rows.
// 128 threads = 4 warps, warp owns 16 q-rows, full DH=64 output in regs.
// Loop over 16 key-tiles of 64: S = Q@K^T (tf32 mma), online softmax in regs,
// P@V via intra-quad shuffle fragment re-layout (no smem round-trip for P).
// ---------------------------------------------------------------------------
__global__ __launch_bounds__(128) void k_flash() {
    constexpr int SKT = 68;   // Kt stride: frag read addr = gid*4+tig -> conflict-free
    constexpr int SVT = 72;   // Vt stride: frag read addr = tig*8+gid -> conflict-free
    __shared__ uint32_t Kt[64 * SKT];   // [key][dh]; also stages Q at start
    __shared__ uint32_t Vt[64 * SVT];   // [key][dh]

    const int bh = blockIdx.y;
    const int q0 = blockIdx.x * 64;
    const float* Qg = g_Q + (size_t)bh * CS * CDH;
    const float* Kg = g_K + (size_t)bh * CS * CDH;
    const float* Vg = g_V + (size_t)bh * CS * CDH;
    const int b = bh >> 4, h = bh & 15;

    const int tid = threadIdx.x;
    const int warp = tid >> 5, lane = tid & 31;
    const int gid = lane >> 2, tig = lane & 3;
    const int wr = warp * 16;

    const int lkey = tid >> 4;          // loader: 8 keys per pass
    const int ldh = (tid & 15) * 4;     // loader: 4 dh per thread

    // ---- stage Q through Kt, pull fragments to registers ----
#pragma unroll
    for (int i = 0; i < 8; i++) {
        int r = lkey + i * 8;
        float4 v = *reinterpret_cast<const float4*>(Qg + (size_t)(q0 + r) * CDH + ldh);
        *reinterpret_cast<uint4*>(&Kt[r * SKT + ldh]) =
            make_uint4(f2tf(v.x), f2tf(v.y), f2tf(v.z), f2tf(v.w));
    }
    __syncthreads();
    uint32_t qf[8][4];
#pragma unroll
    for (int kc = 0; kc < 8; kc++) {
        qf[kc][0] = Kt[(wr + gid) * SKT + kc * 8 + tig];
        qf[kc][1] = Kt[(wr + gid + 8) * SKT + kc * 8 + tig];
        qf[kc][2] = Kt[(wr + gid) * SKT + kc * 8 + tig + 4];
        qf[kc][3] = Kt[(wr + gid + 8) * SKT + kc * 8 + tig + 4];
    }

    float acc[8][4] = {};
    float m0v = -1e30f, m1v = -1e30f, l0 = 0.f, l1 = 0.f;

    for (int kt = 0; kt < CS; kt += 64) {
        __syncthreads();
#pragma unroll
        for (int i = 0; i < 8; i++) {
            int r = lkey + i * 8;
            float4 kv = *reinterpret_cast<const float4*>(Kg + (size_t)(kt + r) * CDH + ldh);
            float4 vv = *reinterpret_cast<const float4*>(Vg + (size_t)(kt + r) * CDH + ldh);
            *reinterpret_cast<uint4*>(&Kt[r * SKT + ldh]) =
                make_uint4(f2tf(kv.x), f2tf(kv.y), f2tf(kv.z), f2tf(kv.w));
            *reinterpret_cast<uint4*>(&Vt[r * SVT + ldh]) =
                make_uint4(f2tf(vv.x), f2tf(vv.y), f2tf(vv.z), f2tf(vv.w));
        }
        __syncthreads();

        // ---- S = Q @ K^T  (16 x 64 per warp) ----
        float S[8][4] = {};
#pragma unroll
        for (int nj = 0; nj < 8; nj++) {
#pragma unroll
            for (int kc = 0; kc < 8; kc++) {
                uint32_t bf[2];
                bf[0] = Kt[(nj * 8 + gid) * SKT + kc * 8 + tig];
                bf[1] = Kt[(nj * 8 + gid) * SKT + kc * 8 + tig + 4];
                mma8(S[nj], qf[kc], bf);
            }
        }

        // ---- online softmax (rows gid and gid+8) ----
        float mx0 = -1e30f, mx1 = -1e30f;
#pragma unroll
        for (int nj = 0; nj < 8; nj++) {
            mx0 = fmaxf(mx0, fmaxf(S[nj][0], S[nj][1]));
            mx1 = fmaxf(mx1, fmaxf(S[nj][2], S[nj][3]));
        }
        mx0 = fmaxf(mx0, __shfl_xor_sync(0xffffffffu, mx0, 1));
        mx0 = fmaxf(mx0, __shfl_xor_sync(0xffffffffu, mx0, 2));
        mx1 = fmaxf(mx1, __shfl_xor_sync(0xffffffffu, mx1, 1));
        mx1 = fmaxf(mx1, __shfl_xor_sync(0xffffffffu, mx1, 2));
        float mn0 = fmaxf(m0v, mx0), mn1 = fmaxf(m1v, mx1);
        float sc0 = __expf(m0v - mn0), sc1 = __expf(m1v - mn1);
        m0v = mn0; m1v = mn1;

        float rs0 = 0.f, rs1 = 0.f;
#pragma unroll
        for (int nj = 0; nj < 8; nj++) {
            S[nj][0] = __expf(S[nj][0] - mn0);
            S[nj][1] = __expf(S[nj][1] - mn0);
            S[nj][2] = __expf(S[nj][2] - mn1);
            S[nj][3] = __expf(S[nj][3] - mn1);
            rs0 += S[nj][0] + S[nj][1];
            rs1 += S[nj][2] + S[nj][3];
        }
        rs0 += __shfl_xor_sync(0xffffffffu, rs0, 1);
        rs0 += __shfl_xor_sync(0xffffffffu, rs0, 2);
        rs1 += __shfl_xor_sync(0xffffffffu, rs1, 1);
        rs1 += __shfl_xor_sync(0xffffffffu, rs1, 2);
        l0 = l0 * sc0 + rs0;
        l1 = l1 * sc1 + rs1;
#pragma unroll
        for (int nj = 0; nj < 8; nj++) {
            acc[nj][0] *= sc0; acc[nj][1] *= sc0;
            acc[nj][2] *= sc1; acc[nj][3] *= sc1;
        }

        // ---- O += P @ V : re-layout C-frag -> A-frag via quad shuffles ----
#pragma unroll
        for (int ks = 0; ks < 8; ks++) {
            uint32_t p0 = f2tf(S[ks][0]), p1 = f2tf(S[ks][1]);
            uint32_t p2 = f2tf(S[ks][2]), p3 = f2tf(S[ks][3]);
            int q = tig >> 1;
            uint32_t w0 = __shfl_sync(0xffffffffu, p0, q, 4);
            uint32_t w1 = __shfl_sync(0xffffffffu, p1, q, 4);
            uint32_t x0 = __shfl_sync(0xffffffffu, p0, q + 2, 4);
            uint32_t x1 = __shfl_sync(0xffffffffu, p1, q + 2, 4);
            uint32_t y0 = __shfl_sync(0xffffffffu, p2, q, 4);
            uint32_t y1 = __shfl_sync(0xffffffffu, p3, q, 4);
            uint32_t z0 = __shfl_sync(0xffffffffu, p2, q + 2, 4);
            uint32_t z1 = __shfl_sync(0xffffffffu, p3, q + 2, 4);
            uint32_t af[4];
            const bool odd = (tig & 1);
            af[0] = odd ? w1 : w0;   // P(gid,    tig)
            af[1] = odd ? y1 : y0;   // P(gid+8,  tig)
            af[2] = odd ? x1 : x0;   // P(gid,    tig+4)
            af[3] = odd ? z1 : z0;   // P(gid+8,  tig+4)
#pragma unroll
            for (int nj = 0; nj < 8; nj++) {
                uint32_t bf[2];
                bf[0] = Vt[(ks * 8 + tig) * SVT + nj * 8 + gid];
                bf[1] = Vt[(ks * 8 + tig + 4) * SVT + nj * 8 + gid];
                mma8(acc[nj], af, bf);
            }
        }
    }

    // ---- normalize + write to g_O [B,S,D] ----
    float inv0 = 1.0f / l0, inv1 = 1.0f / l1;
    int s0 = q0 + wr + gid;
#pragma unroll
    for (int nj = 0; nj < 8; nj++) {
        int col = h * CDH + nj * 8 + 2 * tig;
        float* o0 = g_O + ((size_t)(b * CS + s0)) * CD + col;
        float* o1 = g_O + ((size_t)(b * CS + s0 + 8)) * CD + col;
        *reinterpret_cast<float2*>(o0) = make_float2(acc[nj][0] * inv0, acc[nj][1] * inv0);
        *reinterpret_cast<float2*>(o1) = make_float2(acc[nj][2] * inv1, acc[nj][3] * inv1);
    }
}

// ---------------------------------------------------------------------------
// Launch
// ---------------------------------------------------------------------------
extern "C" void kernel_launch(void* const* d_in, const int* in_sizes, int n_in,
                              void* d_out, int out_size) {
    const float* x    = (const float*)d_in[0];  // [B,S,D]
    const float* Wqkv = (const float*)d_in[1];  // [3D,D]
    const float* Wout = (const float*)d_in[2];  // [D,D]
    float* out = (float*)d_out;                 // [B,S,D]

    (void)in_sizes; (void)n_in; (void)out_size;

    // 1) fused QKV projection -> Q(scaled), K, V  [B,H,S,DH]
    k_gemm_nt<0><<<dim3(CN_QKV / 128, CM / 128), 256>>>(x, Wqkv, nullptr, CD);
    // 2) fused attention (scores + softmax + PV) -> g_O [B,S,D]
    k_flash<<<dim3(CS / 64, CB * CH), 128>>>();
    // 3) output projection -> d_out
    k_gemm_nt<2><<<dim3(CD / 128, CM / 128), 256>>>(nullptr, Wout, out, CD);
}